// round 14
// baseline (speedup 1.0000x reference)
#include <cuda_runtime.h>
#include <cuda_fp16.h>
#include <cstdint>

// ─────────────────────────────────────────────────────────────────────────────
// KPConv: prep (x→fp16, W transpose→fp16) ➜ producer with paired phase 4
// (lanes 0-15 own p0, 16-31 own p1), 7/7/6/6 double-buffered gathers with
// cross-pair prefetch ➜ fp16 HMMA GEMM, 64x64 warp tiles, KT=64, 3-stage ring.
// Two dummy launches shift the ncu-captured launch (#4) onto the producer.
// tcgen05 unavailable (harness PTX target is sm_103, not sm_103a).
// ─────────────────────────────────────────────────────────────────────────────

namespace {

typedef unsigned long long u64;

constexpr int H    = 26;
constexpr int KP   = 10;
constexpr int CIN  = 64;
constexpr int COUT = 128;
constexpr int KDIM = KP * CIN;   // 640
constexpr int TILE = 32;
constexpr int NT   = 256;
constexpr float INV_EXT = 1.0f / 1.2f;
constexpr int MAXN = 65536;

__device__ __half g_A[(size_t)MAXN * KDIM];
__device__ __half g_B[(size_t)COUT * KDIM];   // [o][k*64+i]
__device__ __half g_X[(size_t)MAXN * CIN];    // fp16 copy of x

__device__ __forceinline__ uint32_t smem_u32(const void* p) {
  uint32_t a;
  asm("{ .reg .u64 t; cvta.to.shared.u64 t, %1; cvt.u32.u64 %0, t; }"
      : "=r"(a) : "l"(p));
  return a;
}

__device__ __forceinline__ u64 ffma2(u64 a, u64 b, u64 c) {
  u64 d;
  asm("fma.rn.f32x2 %0, %1, %2, %3;" : "=l"(d) : "l"(a), "l"(b), "l"(c));
  return d;
}
__device__ __forceinline__ u64 pack2(float lo, float hi) {
  u64 d;
  asm("mov.b64 %0, {%1, %2};" : "=l"(d) : "f"(lo), "f"(hi));
  return d;
}
__device__ __forceinline__ float2 unpack2(u64 v) {
  float2 r;
  asm("mov.b64 {%0, %1}, %2;" : "=f"(r.x), "=f"(r.y) : "l"(v));
  return r;
}

__device__ __forceinline__ void cp16(uint32_t dst, const void* src) {
  asm volatile("cp.async.cg.shared.global [%0], [%1], 16;"
               :: "r"(dst), "l"(src) : "memory");
}
__device__ __forceinline__ void cp_commit() {
  asm volatile("cp.async.commit_group;" ::: "memory");
}
__device__ __forceinline__ void cp_wait1() {
  asm volatile("cp.async.wait_group 1;" ::: "memory");
}

__device__ __forceinline__ void ldm4(uint32_t* r, uint32_t addr) {
  asm volatile("ldmatrix.sync.aligned.m8n8.x4.shared.b16 {%0,%1,%2,%3}, [%4];"
               : "=r"(r[0]), "=r"(r[1]), "=r"(r[2]), "=r"(r[3]) : "r"(addr));
}

__device__ __forceinline__ void mma16816(float* d, const uint32_t* a,
                                         const uint32_t* b) {
  asm volatile(
      "mma.sync.aligned.m16n8k16.row.col.f32.f16.f16.f32 "
      "{%0,%1,%2,%3}, {%4,%5,%6,%7}, {%8,%9}, {%0,%1,%2,%3};"
      : "+f"(d[0]), "+f"(d[1]), "+f"(d[2]), "+f"(d[3])
      : "r"(a[0]), "r"(a[1]), "r"(a[2]), "r"(a[3]), "r"(b[0]), "r"(b[1]));
}

// ───────────────────── Dummy (shifts profiled launch onto producer) ─────────────

__global__ void dummy_kernel() {}

// ───────────────────── Kernel 0: prep (x→fp16, W→fp16 transposed) ───────────────

__global__ void prep_kernel(const float* __restrict__ x,
                            const float* __restrict__ weights,
                            int total_x)
{
  const int gid    = blockIdx.x * blockDim.x + threadIdx.x;
  const int stride = gridDim.x * blockDim.x;

  const int nv = total_x / 4;
  const float4* xv = reinterpret_cast<const float4*>(x);
  for (int i = gid; i < nv; i += stride) {
    const float4 v = xv[i];
    __half2* dst = reinterpret_cast<__half2*>(g_X + (size_t)i * 4);
    dst[0] = __floats2half2_rn(v.x, v.y);
    dst[1] = __floats2half2_rn(v.z, v.w);
  }
  for (int t = gid; t < KDIM * COUT; t += stride) {
    const int o  = t / KDIM;
    const int ki = t - o * KDIM;
    g_B[t] = __float2half_rn(weights[(size_t)ki * COUT + o]);
  }
}

// ───────────────────── Kernel 1: producer (paired, double-buffered) ─────────────

struct P1Smem {
  u64   genWT2[42 * 32];
  float genB[32];
  float sP[8][4][84];
  float sKP[8][4][32];
  alignas(16) float swv[8][2][H * 12];   // per pair: [pt][h][k], stride 12
  int   sIdx[8][4][H];
};

__global__ void __launch_bounds__(NT, 3)
producer_kernel(const float* __restrict__ q_pts,
                const float* __restrict__ s_pts,
                const float* __restrict__ genW,
                const float* __restrict__ genB,
                const int*   __restrict__ inds,
                int N, int Ns)
{
  __shared__ P1Smem sm;
  const int tid  = threadIdx.x;
  const int lane = tid & 31;
  const int wid  = tid >> 5;

  for (int t = tid; t < 42 * 32; t += NT) {
    const int j  = t & 31;
    const int m2 = t >> 5;
    sm.genWT2[t] = (j < 30)
        ? pack2(genW[j * 84 + 2 * m2], genW[j * 84 + 2 * m2 + 1]) : 0;
  }
  if (tid < 30) sm.genB[tid] = genB[tid];
  __syncthreads();

  const int nw = blockIdx.x * TILE + wid * 4;

  // ── Phase 1 (batched 4 points); sP/sIdx always written (safe fallbacks). ──
  if (lane < H) {
    int jj[4];
    #pragma unroll
    for (int p = 0; p < 4; ++p) {
      const int n = nw + p;
      jj[p] = (n < N) ? inds[(size_t)n * H + lane] : 0;
    }
    float cx[4], cy[4], cz[4];
    #pragma unroll
    for (int p = 0; p < 4; ++p) {
      int j = jj[p];
      if (j >= 0 && j < Ns) {
        cx[p] = s_pts[3 * j + 0];
        cy[p] = s_pts[3 * j + 1];
        cz[p] = s_pts[3 * j + 2];
      } else {
        cx[p] = cy[p] = cz[p] = 1e6f;   // shadow point -> zero influence
        jj[p] = 0;
      }
    }
    #pragma unroll
    for (int p = 0; p < 4; ++p) {
      const int n = nw + p;
      float qx = 0.f, qy = 0.f, qz = 0.f;
      if (n < N) {
        qx = q_pts[3 * n + 0];
        qy = q_pts[3 * n + 1];
        qz = q_pts[3 * n + 2];
      }
      sm.sP[wid][p][lane * 3 + 0] = cx[p] - qx;
      sm.sP[wid][p][lane * 3 + 1] = cy[p] - qy;
      sm.sP[wid][p][lane * 3 + 2] = cz[p] - qz;
      sm.sIdx[wid][p][lane] = jj[p];
    }
  } else if (lane < 28) {
    const int b = lane - H;
    #pragma unroll
    for (int p = 0; p < 4; ++p) {
      sm.sP[wid][p][78 + b * 3 + 0] = -1.0f;
      sm.sP[wid][p][78 + b * 3 + 1] = -1.0f;
      sm.sP[wid][p][78 + b * 3 + 2] = -1.0f;
    }
  }
  __syncwarp();

  // ── Phase 2 (batched): kp = gen_W @ p_vec + gen_b. ──
  if (lane < 30) {
    u64 aA[4] = {0, 0, 0, 0}, aB[4] = {0, 0, 0, 0};
    const u64* pp0 = reinterpret_cast<const u64*>(&sm.sP[wid][0][0]);
    const u64* pp1 = reinterpret_cast<const u64*>(&sm.sP[wid][1][0]);
    const u64* pp2 = reinterpret_cast<const u64*>(&sm.sP[wid][2][0]);
    const u64* pp3 = reinterpret_cast<const u64*>(&sm.sP[wid][3][0]);
    #pragma unroll 7
    for (int m2 = 0; m2 < 21; ++m2) {
      const u64 wA = sm.genWT2[m2 * 32 + lane];
      const u64 wB = sm.genWT2[(m2 + 21) * 32 + lane];
      aA[0] = ffma2(wA, pp0[m2], aA[0]);  aB[0] = ffma2(wB, pp0[m2 + 21], aB[0]);
      aA[1] = ffma2(wA, pp1[m2], aA[1]);  aB[1] = ffma2(wB, pp1[m2 + 21], aB[1]);
      aA[2] = ffma2(wA, pp2[m2], aA[2]);  aB[2] = ffma2(wB, pp2[m2 + 21], aB[2]);
      aA[3] = ffma2(wA, pp3[m2], aA[3]);  aB[3] = ffma2(wB, pp3[m2 + 21], aB[3]);
    }
    const float gb = sm.genB[lane];
    #pragma unroll
    for (int p = 0; p < 4; ++p) {
      const float2 ra = unpack2(aA[p]);
      const float2 rb = unpack2(aB[p]);
      sm.sKP[wid][p][lane] = (ra.x + ra.y) + (rb.x + rb.y) + gb;
    }
  }
  __syncwarp();

  const int half = lane >> 4;        // which point of the active pair
  const int cg   = lane & 15;        // column group: cols 4*cg .. 4*cg+3

  auto gather = [&](u64* buf, const int* idx, int off, int cnt) {
    #pragma unroll
    for (int hh = 0; hh < 7; ++hh)
      if (hh < cnt)
        buf[hh] = *reinterpret_cast<const u64*>(
            g_X + (size_t)idx[off + hh] * CIN + 4 * cg);
  };

  u64 xP[7], xQ[7];
  // Prologue: prefetch pair 0's first batch (in flight through phase 3).
  gather(xP, &sm.sIdx[wid][half][0], 0, 7);

  // ── Two point-pairs: (0,1) then (2,3). ──
  for (int pp = 0; pp < 2; ++pp) {
    __syncwarp();   // prior pair's swv reads complete before overwrite

    // Phase 3: influence weights for both points of the pair.
    #pragma unroll
    for (int pt = 0; pt < 2; ++pt) {
      const int p = 2 * pp + pt;
      for (int t = lane; t < KP * H; t += 32) {
        const int k = t / H;
        const int h = t - k * H;
        const float dx = sm.sP[wid][p][h * 3 + 0] - sm.sKP[wid][p][k * 3 + 0];
        const float dy = sm.sP[wid][p][h * 3 + 1] - sm.sKP[wid][p][k * 3 + 1];
        const float dz = sm.sP[wid][p][h * 3 + 2] - sm.sKP[wid][p][k * 3 + 2];
        const float d  = sqrtf(fmaf(dx, dx, fmaf(dy, dy, dz * dz)));
        sm.swv[wid][pt][h * 12 + k] = fmaxf(1.0f - d * INV_EXT, 0.0f);
      }
    }
    __syncwarp();

    // Phase 4 (paired): lane handles point (2*pp + half), cols 4cg..4cg+3.
    const int p = 2 * pp + half;
    const int n = nw + p;
    const int* idx = &sm.sIdx[wid][p][0];
    const float* wvp = &sm.swv[wid][half][0];

    u64 acc[5][4];   // [kk][c]: (k=2kk, k=2kk+1) for col 4cg+c
    #pragma unroll
    for (int kk = 0; kk < 5; ++kk)
      #pragma unroll
      for (int c = 0; c < 4; ++c) acc[kk][c] = 0;

    auto accum = [&](const u64* buf, int off, int cnt) {
      #pragma unroll
      for (int hh = 0; hh < 7; ++hh) {
        if (hh >= cnt) break;
        const u64 x8 = buf[hh];
        uint32_t ulo = (uint32_t)x8;
        uint32_t uhi = (uint32_t)(x8 >> 32);
        const float2 f01 = __half22float2(*reinterpret_cast<__half2*>(&ulo));
        const float2 f23 = __half22float2(*reinterpret_cast<__half2*>(&uhi));
        const u64 xc[4] = {pack2(f01.x, f01.x), pack2(f01.y, f01.y),
                           pack2(f23.x, f23.x), pack2(f23.y, f23.y)};
        const u64* wp = reinterpret_cast<const u64*>(wvp + (off + hh) * 12);
        #pragma unroll
        for (int kk = 0; kk < 5; ++kk) {
          const u64 w2 = wp[kk];
          #pragma unroll
          for (int c = 0; c < 4; ++c)
            acc[kk][c] = ffma2(w2, xc[c], acc[kk][c]);
        }
      }
    };

    // Double-buffered batches: 7 / 7 / 6 / 6.
    gather(xQ, idx, 7, 7);
    accum(xP, 0, 7);
    gather(xP, idx, 14, 6);
    accum(xQ, 7, 7);
    gather(xQ, idx, 20, 6);
    accum(xP, 14, 6);
    if (pp == 0)   // cross-pair prefetch: pair 1's batch 0 in flight early
      gather(xP, &sm.sIdx[wid][2 + half][0], 0, 7);
    accum(xQ, 20, 6);

    // Store: per k, 4 fp16 cols per lane -> one 8-B store.
    if (n < N) {
      __half* base = g_A + (size_t)n * KDIM;
      #pragma unroll
      for (int kk = 0; kk < 5; ++kk) {
        const float2 v0 = unpack2(acc[kk][0]);
        const float2 v1 = unpack2(acc[kk][1]);
        const float2 v2 = unpack2(acc[kk][2]);
        const float2 v3 = unpack2(acc[kk][3]);
        const __half2 e01 = __floats2half2_rn(v0.x, v1.x);
        const __half2 e23 = __floats2half2_rn(v2.x, v3.x);
        const __half2 o01 = __floats2half2_rn(v0.y, v1.y);
        const __half2 o23 = __floats2half2_rn(v2.y, v3.y);
        u64 we = ((u64)*reinterpret_cast<const uint32_t*>(&e23) << 32) |
                 *reinterpret_cast<const uint32_t*>(&e01);
        u64 wo = ((u64)*reinterpret_cast<const uint32_t*>(&o23) << 32) |
                 *reinterpret_cast<const uint32_t*>(&o01);
        *reinterpret_cast<u64*>(base + (2 * kk) * CIN + 4 * cg) = we;
        *reinterpret_cast<u64*>(base + (2 * kk + 1) * CIN + 4 * cg) = wo;
      }
    }
  }
}

// ───────────────────── Kernel 2: fp16 mma.sync GEMM (round-12, verbatim) ────────

constexpr int KT      = 64;
constexpr int PITCH   = 144;
constexpr int TSZ     = 128 * PITCH;       // 18432 B
constexpr int STAGE   = 2 * TSZ;           // 36864 B
constexpr int NSTAGES = 3;
constexpr int GSMEM   = NSTAGES * STAGE;   // 110592 B
constexpr int NKT     = KDIM / KT;         // 10
constexpr int GNT     = 128;

__global__ void __launch_bounds__(GNT, 2)
gemm_kernel(float* __restrict__ out, int N)
{
  extern __shared__ char sm[];
  const uint32_t sb = smem_u32(sm);
  const int tid  = threadIdx.x;
  const int lane = tid & 31;
  const int wid  = tid >> 5;
  const int wr   = wid >> 1;
  const int wc   = wid & 1;
  const size_t n0 = (size_t)blockIdx.x * 128;

  auto load_stage = [&](int st, int kc) {
    const uint32_t base = sb + st * STAGE;
    #pragma unroll
    for (int i = 0; i < 8; ++i) {
      const int id = tid + i * GNT;
      const int r  = id >> 3;
      const int c  = id & 7;
      const uint32_t d = r * PITCH + c * 16;
      cp16(base + d,       g_A + (n0 + r) * KDIM + kc * KT + c * 8);
      cp16(base + TSZ + d, g_B + (size_t)r * KDIM + kc * KT + c * 8);
    }
  };

  load_stage(0, 0); cp_commit();
  load_stage(1, 1); cp_commit();

  const int arow  = lane & 15;
  const int acolB = (lane >> 4) * 16;
  const int brow  = (lane & 7) + ((lane >> 4) << 3);
  const int bcolB = ((lane >> 3) & 1) * 16;

  float acc[4][8][4];
  #pragma unroll
  for (int mi = 0; mi < 4; ++mi)
    #pragma unroll
    for (int ni = 0; ni < 8; ++ni)
      #pragma unroll
      for (int j = 0; j < 4; ++j) acc[mi][ni][j] = 0.f;

  for (int kc = 0; kc < NKT; ++kc) {
    const int st = kc % NSTAGES;
    cp_wait1();
    __syncthreads();

    if (kc + 2 < NKT) load_stage((kc + 2) % NSTAGES, kc + 2);
    cp_commit();

    const uint32_t tA = sb + st * STAGE;
    const uint32_t tB = sb + st * STAGE + TSZ;

    #pragma unroll
    for (int ks = 0; ks < 4; ++ks) {
      uint32_t ah[4][4], bh[8][2];
      #pragma unroll
      for (int mi = 0; mi < 4; ++mi) {
        const uint32_t ao =
            (wr * 64 + mi * 16 + arow) * PITCH + ks * 32 + acolB;
        ldm4(ah[mi], tA + ao);
      }
      #pragma unroll
      for (int bi = 0; bi < 4; ++bi) {
        const uint32_t bo =
            (wc * 64 + bi * 16 + brow) * PITCH + ks * 32 + bcolB;
        uint32_t t4[4];
        ldm4(t4, tB + bo);
        bh[2 * bi][0] = t4[0]; bh[2 * bi][1] = t4[1];
        bh[2 * bi + 1][0] = t4[2]; bh[2 * bi + 1][1] = t4[3];
      }
      #pragma unroll
      for (int mi = 0; mi < 4; ++mi)
        #pragma unroll
        for (int ni = 0; ni < 8; ++ni)
          mma16816(acc[mi][ni], ah[mi], bh[ni]);
    }
  }

  const int trow = lane >> 2;
  const int tcol = (lane & 3) * 2;
  #pragma unroll
  for (int mi = 0; mi < 4; ++mi) {
    const size_t row = n0 + wr * 64 + mi * 16 + trow;
    #pragma unroll
    for (int ni = 0; ni < 8; ++ni) {
      const int col = wc * 64 + ni * 8 + tcol;
      if (row < (size_t)N) {
        *reinterpret_cast<float2*>(out + row * COUT + col) =
            make_float2(acc[mi][ni][0], acc[mi][ni][1]);
        *reinterpret_cast<float2*>(out + (row + 8) * COUT + col) =
            make_float2(acc[mi][ni][2], acc[mi][ni][3]);
      }
    }
  }
}

}  // namespace

// ───────────────────────────── launch ─────────────────────────────

extern "C" void kernel_launch(void* const* d_in, const int* in_sizes, int n_in,
                              void* d_out, int out_size) {
  const float* q_pts = (const float*)d_in[0];
  const float* s_pts = (const float*)d_in[1];
  const float* x     = (const float*)d_in[2];
  const float* genW  = (const float*)d_in[3];
  const float* genB  = (const float*)d_in[4];
  const float* wts   = (const float*)d_in[5];
  const int*   inds  = (const int*)d_in[6];
  float* out = (float*)d_out;

  int N  = in_sizes[0] / 3;
  const int Ns = in_sizes[1] / 3;
  if (N > MAXN) N = MAXN;

  cudaFuncSetAttribute(gemm_kernel,
                       cudaFuncAttributeMaxDynamicSharedMemorySize, GSMEM);

  // Launch-position shims: make the ncu-captured launch (#4) the producer.
  dummy_kernel<<<1, 32>>>();
  dummy_kernel<<<1, 32>>>();

  prep_kernel<<<1024, 256>>>(x, wts, N * CIN);

  const int grid1 = (N + TILE - 1) / TILE;
  producer_kernel<<<grid1, NT>>>(q_pts, s_pts, genW, genB, inds, N, Ns);

  const int grid3 = (N + 127) / 128;
  gemm_kernel<<<grid3, GNT, GSMEM>>>(out, N);
}

// round 15
// speedup vs baseline: 1.0546x; 1.0546x over previous
#include <cuda_runtime.h>
#include <cuda_fp16.h>
#include <cstdint>

// ─────────────────────────────────────────────────────────────────────────────
// KPConv: prep (x→fp16, W transpose→fp16) ➜ producer with paired phase 4;
// L1-traffic cuts: LDS.128 weight broadcasts + conflict-free h-major phase-3
// stores (producer measured L1tex-bound: 69.6% L1, 43% fma)
// ➜ fp16 HMMA GEMM, 64x64 warp tiles, KT=64, 3-stage cp.async ring.
// tcgen05 unavailable (harness PTX target is sm_103, not sm_103a).
// ─────────────────────────────────────────────────────────────────────────────

namespace {

typedef unsigned long long u64;

constexpr int H    = 26;
constexpr int KP   = 10;
constexpr int CIN  = 64;
constexpr int COUT = 128;
constexpr int KDIM = KP * CIN;   // 640
constexpr int TILE = 32;
constexpr int NT   = 256;
constexpr float INV_EXT = 1.0f / 1.2f;
constexpr int MAXN = 65536;

__device__ __half g_A[(size_t)MAXN * KDIM];
__device__ __half g_B[(size_t)COUT * KDIM];   // [o][k*64+i]
__device__ __half g_X[(size_t)MAXN * CIN];    // fp16 copy of x

__device__ __forceinline__ uint32_t smem_u32(const void* p) {
  uint32_t a;
  asm("{ .reg .u64 t; cvta.to.shared.u64 t, %1; cvt.u32.u64 %0, t; }"
      : "=r"(a) : "l"(p));
  return a;
}

__device__ __forceinline__ u64 ffma2(u64 a, u64 b, u64 c) {
  u64 d;
  asm("fma.rn.f32x2 %0, %1, %2, %3;" : "=l"(d) : "l"(a), "l"(b), "l"(c));
  return d;
}
__device__ __forceinline__ u64 pack2(float lo, float hi) {
  u64 d;
  asm("mov.b64 %0, {%1, %2};" : "=l"(d) : "f"(lo), "f"(hi));
  return d;
}
__device__ __forceinline__ float2 unpack2(u64 v) {
  float2 r;
  asm("mov.b64 {%0, %1}, %2;" : "=f"(r.x), "=f"(r.y) : "l"(v));
  return r;
}
__device__ __forceinline__ u64 cat2(uint32_t lo, uint32_t hi) {
  u64 d;
  asm("mov.b64 %0, {%1, %2};" : "=l"(d) : "r"(lo), "r"(hi));
  return d;
}

__device__ __forceinline__ void cp16(uint32_t dst, const void* src) {
  asm volatile("cp.async.cg.shared.global [%0], [%1], 16;"
               :: "r"(dst), "l"(src) : "memory");
}
__device__ __forceinline__ void cp_commit() {
  asm volatile("cp.async.commit_group;" ::: "memory");
}
__device__ __forceinline__ void cp_wait1() {
  asm volatile("cp.async.wait_group 1;" ::: "memory");
}

__device__ __forceinline__ void ldm4(uint32_t* r, uint32_t addr) {
  asm volatile("ldmatrix.sync.aligned.m8n8.x4.shared.b16 {%0,%1,%2,%3}, [%4];"
               : "=r"(r[0]), "=r"(r[1]), "=r"(r[2]), "=r"(r[3]) : "r"(addr));
}

__device__ __forceinline__ void mma16816(float* d, const uint32_t* a,
                                         const uint32_t* b) {
  asm volatile(
      "mma.sync.aligned.m16n8k16.row.col.f32.f16.f16.f32 "
      "{%0,%1,%2,%3}, {%4,%5,%6,%7}, {%8,%9}, {%0,%1,%2,%3};"
      : "+f"(d[0]), "+f"(d[1]), "+f"(d[2]), "+f"(d[3])
      : "r"(a[0]), "r"(a[1]), "r"(a[2]), "r"(a[3]), "r"(b[0]), "r"(b[1]));
}

// ───────────────────── Kernel 0: prep (x→fp16, W→fp16 transposed) ───────────────

__global__ void prep_kernel(const float* __restrict__ x,
                            const float* __restrict__ weights,
                            int total_x)
{
  const int gid    = blockIdx.x * blockDim.x + threadIdx.x;
  const int stride = gridDim.x * blockDim.x;

  const int nv = total_x / 4;
  const float4* xv = reinterpret_cast<const float4*>(x);
  for (int i = gid; i < nv; i += stride) {
    const float4 v = xv[i];
    __half2* dst = reinterpret_cast<__half2*>(g_X + (size_t)i * 4);
    dst[0] = __floats2half2_rn(v.x, v.y);
    dst[1] = __floats2half2_rn(v.z, v.w);
  }
  for (int t = gid; t < KDIM * COUT; t += stride) {
    const int o  = t / KDIM;
    const int ki = t - o * KDIM;
    g_B[t] = __float2half_rn(weights[(size_t)ki * COUT + o]);
  }
}

// ───────────────────── Kernel 1: producer (paired phase 4) ─────────────────────

struct P1Smem {
  u64   genWT2[42 * 32];
  float genB[32];
  float sP[8][4][84];
  float sKP[8][4][32];
  alignas(16) float swv[8][2][H * 12];   // per pair: [pt][h][k], stride 12
  int   sIdx[8][4][H];
};

__global__ void __launch_bounds__(NT, 3)
producer_kernel(const float* __restrict__ q_pts,
                const float* __restrict__ s_pts,
                const float* __restrict__ genW,
                const float* __restrict__ genB,
                const int*   __restrict__ inds,
                int N, int Ns)
{
  __shared__ P1Smem sm;
  const int tid  = threadIdx.x;
  const int lane = tid & 31;
  const int wid  = tid >> 5;

  for (int t = tid; t < 42 * 32; t += NT) {
    const int j  = t & 31;
    const int m2 = t >> 5;
    sm.genWT2[t] = (j < 30)
        ? pack2(genW[j * 84 + 2 * m2], genW[j * 84 + 2 * m2 + 1]) : 0;
  }
  if (tid < 30) sm.genB[tid] = genB[tid];
  __syncthreads();

  const int nw = blockIdx.x * TILE + wid * 4;

  // ── Phase 1 (batched 4 points); sP/sIdx always written (safe fallbacks). ──
  if (lane < H) {
    int jj[4];
    #pragma unroll
    for (int p = 0; p < 4; ++p) {
      const int n = nw + p;
      jj[p] = (n < N) ? inds[(size_t)n * H + lane] : 0;
    }
    float cx[4], cy[4], cz[4];
    #pragma unroll
    for (int p = 0; p < 4; ++p) {
      int j = jj[p];
      if (j >= 0 && j < Ns) {
        cx[p] = s_pts[3 * j + 0];
        cy[p] = s_pts[3 * j + 1];
        cz[p] = s_pts[3 * j + 2];
      } else {
        cx[p] = cy[p] = cz[p] = 1e6f;   // shadow point -> zero influence
        jj[p] = 0;
      }
    }
    #pragma unroll
    for (int p = 0; p < 4; ++p) {
      const int n = nw + p;
      float qx = 0.f, qy = 0.f, qz = 0.f;
      if (n < N) {
        qx = q_pts[3 * n + 0];
        qy = q_pts[3 * n + 1];
        qz = q_pts[3 * n + 2];
      }
      sm.sP[wid][p][lane * 3 + 0] = cx[p] - qx;
      sm.sP[wid][p][lane * 3 + 1] = cy[p] - qy;
      sm.sP[wid][p][lane * 3 + 2] = cz[p] - qz;
      sm.sIdx[wid][p][lane] = jj[p];
    }
  } else if (lane < 28) {
    const int b = lane - H;
    #pragma unroll
    for (int p = 0; p < 4; ++p) {
      sm.sP[wid][p][78 + b * 3 + 0] = -1.0f;
      sm.sP[wid][p][78 + b * 3 + 1] = -1.0f;
      sm.sP[wid][p][78 + b * 3 + 2] = -1.0f;
    }
  }
  __syncwarp();

  // ── Phase 2 (batched): kp = gen_W @ p_vec + gen_b. ──
  if (lane < 30) {
    u64 aA[4] = {0, 0, 0, 0}, aB[4] = {0, 0, 0, 0};
    const u64* pp0 = reinterpret_cast<const u64*>(&sm.sP[wid][0][0]);
    const u64* pp1 = reinterpret_cast<const u64*>(&sm.sP[wid][1][0]);
    const u64* pp2 = reinterpret_cast<const u64*>(&sm.sP[wid][2][0]);
    const u64* pp3 = reinterpret_cast<const u64*>(&sm.sP[wid][3][0]);
    #pragma unroll 7
    for (int m2 = 0; m2 < 21; ++m2) {
      const u64 wA = sm.genWT2[m2 * 32 + lane];
      const u64 wB = sm.genWT2[(m2 + 21) * 32 + lane];
      aA[0] = ffma2(wA, pp0[m2], aA[0]);  aB[0] = ffma2(wB, pp0[m2 + 21], aB[0]);
      aA[1] = ffma2(wA, pp1[m2], aA[1]);  aB[1] = ffma2(wB, pp1[m2 + 21], aB[1]);
      aA[2] = ffma2(wA, pp2[m2], aA[2]);  aB[2] = ffma2(wB, pp2[m2 + 21], aB[2]);
      aA[3] = ffma2(wA, pp3[m2], aA[3]);  aB[3] = ffma2(wB, pp3[m2 + 21], aB[3]);
    }
    const float gb = sm.genB[lane];
    #pragma unroll
    for (int p = 0; p < 4; ++p) {
      const float2 ra = unpack2(aA[p]);
      const float2 rb = unpack2(aB[p]);
      sm.sKP[wid][p][lane] = (ra.x + ra.y) + (rb.x + rb.y) + gb;
    }
  }
  __syncwarp();

  const int half = lane >> 4;        // which point of the active pair
  const int cg   = lane & 15;        // column group: cols 4*cg .. 4*cg+3

  // ── Two point-pairs: (0,1) then (2,3). ──
  for (int pp = 0; pp < 2; ++pp) {
    __syncwarp();   // prior pair's swv reads complete before overwrite

    // Phase 3 (h-major lane mapping: consecutive lanes -> consecutive words,
    // conflict-free STS).
    #pragma unroll
    for (int pt = 0; pt < 2; ++pt) {
      const int p = 2 * pp + pt;
      for (int t = lane; t < KP * H; t += 32) {
        const int h = t / KP;
        const int k = t - h * KP;
        const float dx = sm.sP[wid][p][h * 3 + 0] - sm.sKP[wid][p][k * 3 + 0];
        const float dy = sm.sP[wid][p][h * 3 + 1] - sm.sKP[wid][p][k * 3 + 1];
        const float dz = sm.sP[wid][p][h * 3 + 2] - sm.sKP[wid][p][k * 3 + 2];
        const float d  = sqrtf(fmaf(dx, dx, fmaf(dy, dy, dz * dz)));
        sm.swv[wid][pt][h * 12 + k] = fmaxf(1.0f - d * INV_EXT, 0.0f);
      }
    }
    __syncwarp();

    // Phase 4 (paired): lane handles point (2*pp + half), cols 4cg..4cg+3.
    const int p = 2 * pp + half;
    const int n = nw + p;
    const int* idx = &sm.sIdx[wid][p][0];
    const float* wvp = &sm.swv[wid][half][0];

    u64 acc[5][4];   // [kk][c]: (k=2kk, k=2kk+1) for col 4cg+c
    #pragma unroll
    for (int kk = 0; kk < 5; ++kk)
      #pragma unroll
      for (int c = 0; c < 4; ++c) acc[kk][c] = 0;

    auto accum = [&](int h, u64 x8) {
      uint32_t ulo = (uint32_t)x8;
      uint32_t uhi = (uint32_t)(x8 >> 32);
      const float2 f01 = __half22float2(*reinterpret_cast<__half2*>(&ulo));
      const float2 f23 = __half22float2(*reinterpret_cast<__half2*>(&uhi));
      const u64 xc[4] = {pack2(f01.x, f01.x), pack2(f01.y, f01.y),
                         pack2(f23.x, f23.x), pack2(f23.y, f23.y)};
      // Wide weight broadcasts: 2x LDS.128 + 1x LDS.64 (aligned: stride 48B).
      const uint4 wa = *reinterpret_cast<const uint4*>(wvp + h * 12);
      const uint4 wb = *reinterpret_cast<const uint4*>(wvp + h * 12 + 4);
      const u64 w2[5] = {cat2(wa.x, wa.y), cat2(wa.z, wa.w),
                         cat2(wb.x, wb.y), cat2(wb.z, wb.w),
                         *reinterpret_cast<const u64*>(wvp + h * 12 + 8)};
      #pragma unroll
      for (int kk = 0; kk < 5; ++kk)
        #pragma unroll
        for (int c = 0; c < 4; ++c)
          acc[kk][c] = ffma2(w2[kk], xc[c], acc[kk][c]);
    };

    // MLP-batched gathers: 9 / 9 / 8 rows in flight.
    u64 xb[9], xc2[9];
    #pragma unroll
    for (int hh = 0; hh < 9; ++hh)
      xb[hh] = *reinterpret_cast<const u64*>(
          g_X + (size_t)idx[hh] * CIN + 4 * cg);
    #pragma unroll
    for (int hh = 0; hh < 9; ++hh)
      xc2[hh] = *reinterpret_cast<const u64*>(
          g_X + (size_t)idx[9 + hh] * CIN + 4 * cg);
    #pragma unroll
    for (int hh = 0; hh < 9; ++hh) accum(hh, xb[hh]);
    #pragma unroll
    for (int hh = 0; hh < 8; ++hh)
      xb[hh] = *reinterpret_cast<const u64*>(
          g_X + (size_t)idx[18 + hh] * CIN + 4 * cg);
    #pragma unroll
    for (int hh = 0; hh < 9; ++hh) accum(9 + hh, xc2[hh]);
    #pragma unroll
    for (int hh = 0; hh < 8; ++hh) accum(18 + hh, xb[hh]);

    // Store: per k, 4 fp16 cols per lane -> one 8-B store.
    if (n < N) {
      __half* base = g_A + (size_t)n * KDIM;
      #pragma unroll
      for (int kk = 0; kk < 5; ++kk) {
        const float2 v0 = unpack2(acc[kk][0]);
        const float2 v1 = unpack2(acc[kk][1]);
        const float2 v2 = unpack2(acc[kk][2]);
        const float2 v3 = unpack2(acc[kk][3]);
        const __half2 e01 = __floats2half2_rn(v0.x, v1.x);
        const __half2 e23 = __floats2half2_rn(v2.x, v3.x);
        const __half2 o01 = __floats2half2_rn(v0.y, v1.y);
        const __half2 o23 = __floats2half2_rn(v2.y, v3.y);
        u64 we = cat2(*reinterpret_cast<const uint32_t*>(&e01),
                      *reinterpret_cast<const uint32_t*>(&e23));
        u64 wo = cat2(*reinterpret_cast<const uint32_t*>(&o01),
                      *reinterpret_cast<const uint32_t*>(&o23));
        *reinterpret_cast<u64*>(base + (2 * kk) * CIN + 4 * cg) = we;
        *reinterpret_cast<u64*>(base + (2 * kk + 1) * CIN + 4 * cg) = wo;
      }
    }
  }
}

// ───────────────────── Kernel 2: fp16 mma.sync GEMM (round-12, verbatim) ────────

constexpr int KT      = 64;
constexpr int PITCH   = 144;
constexpr int TSZ     = 128 * PITCH;       // 18432 B
constexpr int STAGE   = 2 * TSZ;           // 36864 B
constexpr int NSTAGES = 3;
constexpr int GSMEM   = NSTAGES * STAGE;   // 110592 B
constexpr int NKT     = KDIM / KT;         // 10
constexpr int GNT     = 128;

__global__ void __launch_bounds__(GNT, 2)
gemm_kernel(float* __restrict__ out, int N)
{
  extern __shared__ char sm[];
  const uint32_t sb = smem_u32(sm);
  const int tid  = threadIdx.x;
  const int lane = tid & 31;
  const int wid  = tid >> 5;
  const int wr   = wid >> 1;
  const int wc   = wid & 1;
  const size_t n0 = (size_t)blockIdx.x * 128;

  auto load_stage = [&](int st, int kc) {
    const uint32_t base = sb + st * STAGE;
    #pragma unroll
    for (int i = 0; i < 8; ++i) {
      const int id = tid + i * GNT;
      const int r  = id >> 3;
      const int c  = id & 7;
      const uint32_t d = r * PITCH + c * 16;
      cp16(base + d,       g_A + (n0 + r) * KDIM + kc * KT + c * 8);
      cp16(base + TSZ + d, g_B + (size_t)r * KDIM + kc * KT + c * 8);
    }
  };

  load_stage(0, 0); cp_commit();
  load_stage(1, 1); cp_commit();

  const int arow  = lane & 15;
  const int acolB = (lane >> 4) * 16;
  const int brow  = (lane & 7) + ((lane >> 4) << 3);
  const int bcolB = ((lane >> 3) & 1) * 16;

  float acc[4][8][4];
  #pragma unroll
  for (int mi = 0; mi < 4; ++mi)
    #pragma unroll
    for (int ni = 0; ni < 8; ++ni)
      #pragma unroll
      for (int j = 0; j < 4; ++j) acc[mi][ni][j] = 0.f;

  for (int kc = 0; kc < NKT; ++kc) {
    const int st = kc % NSTAGES;
    cp_wait1();
    __syncthreads();

    if (kc + 2 < NKT) load_stage((kc + 2) % NSTAGES, kc + 2);
    cp_commit();

    const uint32_t tA = sb + st * STAGE;
    const uint32_t tB = sb + st * STAGE + TSZ;

    #pragma unroll
    for (int ks = 0; ks < 4; ++ks) {
      uint32_t ah[4][4], bh[8][2];
      #pragma unroll
      for (int mi = 0; mi < 4; ++mi) {
        const uint32_t ao =
            (wr * 64 + mi * 16 + arow) * PITCH + ks * 32 + acolB;
        ldm4(ah[mi], tA + ao);
      }
      #pragma unroll
      for (int bi = 0; bi < 4; ++bi) {
        const uint32_t bo =
            (wc * 64 + bi * 16 + brow) * PITCH + ks * 32 + bcolB;
        uint32_t t4[4];
        ldm4(t4, tB + bo);
        bh[2 * bi][0] = t4[0]; bh[2 * bi][1] = t4[1];
        bh[2 * bi + 1][0] = t4[2]; bh[2 * bi + 1][1] = t4[3];
      }
      #pragma unroll
      for (int mi = 0; mi < 4; ++mi)
        #pragma unroll
        for (int ni = 0; ni < 8; ++ni)
          mma16816(acc[mi][ni], ah[mi], bh[ni]);
    }
  }

  const int trow = lane >> 2;
  const int tcol = (lane & 3) * 2;
  #pragma unroll
  for (int mi = 0; mi < 4; ++mi) {
    const size_t row = n0 + wr * 64 + mi * 16 + trow;
    #pragma unroll
    for (int ni = 0; ni < 8; ++ni) {
      const int col = wc * 64 + ni * 8 + tcol;
      if (row < (size_t)N) {
        *reinterpret_cast<float2*>(out + row * COUT + col) =
            make_float2(acc[mi][ni][0], acc[mi][ni][1]);
        *reinterpret_cast<float2*>(out + (row + 8) * COUT + col) =
            make_float2(acc[mi][ni][2], acc[mi][ni][3]);
      }
    }
  }
}

}  // namespace

// ───────────────────────────── launch ─────────────────────────────

extern "C" void kernel_launch(void* const* d_in, const int* in_sizes, int n_in,
                              void* d_out, int out_size) {
  const float* q_pts = (const float*)d_in[0];
  const float* s_pts = (const float*)d_in[1];
  const float* x     = (const float*)d_in[2];
  const float* genW  = (const float*)d_in[3];
  const float* genB  = (const float*)d_in[4];
  const float* wts   = (const float*)d_in[5];
  const int*   inds  = (const int*)d_in[6];
  float* out = (float*)d_out;

  int N  = in_sizes[0] / 3;
  const int Ns = in_sizes[1] / 3;
  if (N > MAXN) N = MAXN;

  cudaFuncSetAttribute(gemm_kernel,
                       cudaFuncAttributeMaxDynamicSharedMemorySize, GSMEM);

  prep_kernel<<<1024, 256>>>(x, wts, N * CIN);

  const int grid1 = (N + TILE - 1) / TILE;
  producer_kernel<<<grid1, NT>>>(q_pts, s_pts, genW, genB, inds, N, Ns);

  const int grid3 = (N + 127) / 128;
  gemm_kernel<<<grid3, GNT, GSMEM>>>(out, N);
}

// round 16
// speedup vs baseline: 1.0606x; 1.0057x over previous
#include <cuda_runtime.h>
#include <cuda_fp16.h>
#include <cstdint>

// ─────────────────────────────────────────────────────────────────────────────
// KPConv: prep (x→fp16, W transpose→fp16) ➜ producer with paired phase 4,
// 4-wide double-buffered gathers (16 buffer regs) to fit 64 regs ->
// __launch_bounds__(256,4) = 32 warps/SM (producer measured warp-starved:
// occ 34%, issue 53%) ➜ fp16 HMMA GEMM, 64x64 warp tiles, KT=64, 3-stage ring.
// tcgen05 unavailable (harness PTX target is sm_103, not sm_103a).
// ─────────────────────────────────────────────────────────────────────────────

namespace {

typedef unsigned long long u64;

constexpr int H    = 26;
constexpr int KP   = 10;
constexpr int CIN  = 64;
constexpr int COUT = 128;
constexpr int KDIM = KP * CIN;   // 640
constexpr int TILE = 32;
constexpr int NT   = 256;
constexpr float INV_EXT = 1.0f / 1.2f;
constexpr int MAXN = 65536;

__device__ __half g_A[(size_t)MAXN * KDIM];
__device__ __half g_B[(size_t)COUT * KDIM];   // [o][k*64+i]
__device__ __half g_X[(size_t)MAXN * CIN];    // fp16 copy of x

__device__ __forceinline__ uint32_t smem_u32(const void* p) {
  uint32_t a;
  asm("{ .reg .u64 t; cvta.to.shared.u64 t, %1; cvt.u32.u64 %0, t; }"
      : "=r"(a) : "l"(p));
  return a;
}

__device__ __forceinline__ u64 ffma2(u64 a, u64 b, u64 c) {
  u64 d;
  asm("fma.rn.f32x2 %0, %1, %2, %3;" : "=l"(d) : "l"(a), "l"(b), "l"(c));
  return d;
}
__device__ __forceinline__ u64 pack2(float lo, float hi) {
  u64 d;
  asm("mov.b64 %0, {%1, %2};" : "=l"(d) : "f"(lo), "f"(hi));
  return d;
}
__device__ __forceinline__ float2 unpack2(u64 v) {
  float2 r;
  asm("mov.b64 {%0, %1}, %2;" : "=f"(r.x), "=f"(r.y) : "l"(v));
  return r;
}
__device__ __forceinline__ u64 cat2(uint32_t lo, uint32_t hi) {
  u64 d;
  asm("mov.b64 %0, {%1, %2};" : "=l"(d) : "r"(lo), "r"(hi));
  return d;
}

__device__ __forceinline__ void cp16(uint32_t dst, const void* src) {
  asm volatile("cp.async.cg.shared.global [%0], [%1], 16;"
               :: "r"(dst), "l"(src) : "memory");
}
__device__ __forceinline__ void cp_commit() {
  asm volatile("cp.async.commit_group;" ::: "memory");
}
__device__ __forceinline__ void cp_wait1() {
  asm volatile("cp.async.wait_group 1;" ::: "memory");
}

__device__ __forceinline__ void ldm4(uint32_t* r, uint32_t addr) {
  asm volatile("ldmatrix.sync.aligned.m8n8.x4.shared.b16 {%0,%1,%2,%3}, [%4];"
               : "=r"(r[0]), "=r"(r[1]), "=r"(r[2]), "=r"(r[3]) : "r"(addr));
}

__device__ __forceinline__ void mma16816(float* d, const uint32_t* a,
                                         const uint32_t* b) {
  asm volatile(
      "mma.sync.aligned.m16n8k16.row.col.f32.f16.f16.f32 "
      "{%0,%1,%2,%3}, {%4,%5,%6,%7}, {%8,%9}, {%0,%1,%2,%3};"
      : "+f"(d[0]), "+f"(d[1]), "+f"(d[2]), "+f"(d[3])
      : "r"(a[0]), "r"(a[1]), "r"(a[2]), "r"(a[3]), "r"(b[0]), "r"(b[1]));
}

// ───────────────────── Kernel 0: prep (x→fp16, W→fp16 transposed) ───────────────

__global__ void prep_kernel(const float* __restrict__ x,
                            const float* __restrict__ weights,
                            int total_x)
{
  const int gid    = blockIdx.x * blockDim.x + threadIdx.x;
  const int stride = gridDim.x * blockDim.x;

  const int nv = total_x / 4;
  const float4* xv = reinterpret_cast<const float4*>(x);
  for (int i = gid; i < nv; i += stride) {
    const float4 v = xv[i];
    __half2* dst = reinterpret_cast<__half2*>(g_X + (size_t)i * 4);
    dst[0] = __floats2half2_rn(v.x, v.y);
    dst[1] = __floats2half2_rn(v.z, v.w);
  }
  for (int t = gid; t < KDIM * COUT; t += stride) {
    const int o  = t / KDIM;
    const int ki = t - o * KDIM;
    g_B[t] = __float2half_rn(weights[(size_t)ki * COUT + o]);
  }
}

// ───────────────────── Kernel 1: producer (paired, occ-4) ─────────────────────

struct P1Smem {
  u64   genWT2[42 * 32];
  float genB[32];
  float sP[8][4][84];
  float sKP[8][4][32];
  alignas(16) float swv[8][2][H * 12];   // per pair: [pt][h][k], stride 12
  int   sIdx[8][4][H];
};

__global__ void __launch_bounds__(NT, 4)
producer_kernel(const float* __restrict__ q_pts,
                const float* __restrict__ s_pts,
                const float* __restrict__ genW,
                const float* __restrict__ genB,
                const int*   __restrict__ inds,
                int N, int Ns)
{
  __shared__ P1Smem sm;
  const int tid  = threadIdx.x;
  const int lane = tid & 31;
  const int wid  = tid >> 5;

  for (int t = tid; t < 42 * 32; t += NT) {
    const int j  = t & 31;
    const int m2 = t >> 5;
    sm.genWT2[t] = (j < 30)
        ? pack2(genW[j * 84 + 2 * m2], genW[j * 84 + 2 * m2 + 1]) : 0;
  }
  if (tid < 30) sm.genB[tid] = genB[tid];
  __syncthreads();

  const int nw = blockIdx.x * TILE + wid * 4;

  // ── Phase 1 (batched 4 points); sP/sIdx always written (safe fallbacks). ──
  if (lane < H) {
    int jj[4];
    #pragma unroll
    for (int p = 0; p < 4; ++p) {
      const int n = nw + p;
      jj[p] = (n < N) ? inds[(size_t)n * H + lane] : 0;
    }
    float cx[4], cy[4], cz[4];
    #pragma unroll
    for (int p = 0; p < 4; ++p) {
      int j = jj[p];
      if (j >= 0 && j < Ns) {
        cx[p] = s_pts[3 * j + 0];
        cy[p] = s_pts[3 * j + 1];
        cz[p] = s_pts[3 * j + 2];
      } else {
        cx[p] = cy[p] = cz[p] = 1e6f;   // shadow point -> zero influence
        jj[p] = 0;
      }
    }
    #pragma unroll
    for (int p = 0; p < 4; ++p) {
      const int n = nw + p;
      float qx = 0.f, qy = 0.f, qz = 0.f;
      if (n < N) {
        qx = q_pts[3 * n + 0];
        qy = q_pts[3 * n + 1];
        qz = q_pts[3 * n + 2];
      }
      sm.sP[wid][p][lane * 3 + 0] = cx[p] - qx;
      sm.sP[wid][p][lane * 3 + 1] = cy[p] - qy;
      sm.sP[wid][p][lane * 3 + 2] = cz[p] - qz;
      sm.sIdx[wid][p][lane] = jj[p];
    }
  } else if (lane < 28) {
    const int b = lane - H;
    #pragma unroll
    for (int p = 0; p < 4; ++p) {
      sm.sP[wid][p][78 + b * 3 + 0] = -1.0f;
      sm.sP[wid][p][78 + b * 3 + 1] = -1.0f;
      sm.sP[wid][p][78 + b * 3 + 2] = -1.0f;
    }
  }
  __syncwarp();

  // ── Phase 2 (batched): kp = gen_W @ p_vec + gen_b. ──
  if (lane < 30) {
    u64 aA[4] = {0, 0, 0, 0}, aB[4] = {0, 0, 0, 0};
    const u64* pp0 = reinterpret_cast<const u64*>(&sm.sP[wid][0][0]);
    const u64* pp1 = reinterpret_cast<const u64*>(&sm.sP[wid][1][0]);
    const u64* pp2 = reinterpret_cast<const u64*>(&sm.sP[wid][2][0]);
    const u64* pp3 = reinterpret_cast<const u64*>(&sm.sP[wid][3][0]);
    #pragma unroll 7
    for (int m2 = 0; m2 < 21; ++m2) {
      const u64 wA = sm.genWT2[m2 * 32 + lane];
      const u64 wB = sm.genWT2[(m2 + 21) * 32 + lane];
      aA[0] = ffma2(wA, pp0[m2], aA[0]);  aB[0] = ffma2(wB, pp0[m2 + 21], aB[0]);
      aA[1] = ffma2(wA, pp1[m2], aA[1]);  aB[1] = ffma2(wB, pp1[m2 + 21], aB[1]);
      aA[2] = ffma2(wA, pp2[m2], aA[2]);  aB[2] = ffma2(wB, pp2[m2 + 21], aB[2]);
      aA[3] = ffma2(wA, pp3[m2], aA[3]);  aB[3] = ffma2(wB, pp3[m2 + 21], aB[3]);
    }
    const float gb = sm.genB[lane];
    #pragma unroll
    for (int p = 0; p < 4; ++p) {
      const float2 ra = unpack2(aA[p]);
      const float2 rb = unpack2(aB[p]);
      sm.sKP[wid][p][lane] = (ra.x + ra.y) + (rb.x + rb.y) + gb;
    }
  }
  __syncwarp();

  const int half = lane >> 4;        // which point of the active pair
  const int cg   = lane & 15;        // column group: cols 4*cg .. 4*cg+3

  // ── Two point-pairs: (0,1) then (2,3). ──
  for (int pp = 0; pp < 2; ++pp) {
    __syncwarp();   // prior pair's swv reads complete before overwrite

    // Phase 3 (h-major lane mapping: conflict-free STS).
    #pragma unroll
    for (int pt = 0; pt < 2; ++pt) {
      const int p = 2 * pp + pt;
      for (int t = lane; t < KP * H; t += 32) {
        const int h = t / KP;
        const int k = t - h * KP;
        const float dx = sm.sP[wid][p][h * 3 + 0] - sm.sKP[wid][p][k * 3 + 0];
        const float dy = sm.sP[wid][p][h * 3 + 1] - sm.sKP[wid][p][k * 3 + 1];
        const float dz = sm.sP[wid][p][h * 3 + 2] - sm.sKP[wid][p][k * 3 + 2];
        const float d  = sqrtf(fmaf(dx, dx, fmaf(dy, dy, dz * dz)));
        sm.swv[wid][pt][h * 12 + k] = fmaxf(1.0f - d * INV_EXT, 0.0f);
      }
    }
    __syncwarp();

    // Phase 4 (paired): lane handles point (2*pp + half), cols 4cg..4cg+3.
    const int p = 2 * pp + half;
    const int n = nw + p;
    const int* idx = &sm.sIdx[wid][p][0];
    const float* wvp = &sm.swv[wid][half][0];

    u64 acc[5][4];   // [kk][c]: (k=2kk, k=2kk+1) for col 4cg+c
    #pragma unroll
    for (int kk = 0; kk < 5; ++kk)
      #pragma unroll
      for (int c = 0; c < 4; ++c) acc[kk][c] = 0;

    auto gather = [&](u64* buf, int off, int cnt) {
      #pragma unroll
      for (int hh = 0; hh < 4; ++hh)
        if (hh < cnt)
          buf[hh] = *reinterpret_cast<const u64*>(
              g_X + (size_t)idx[off + hh] * CIN + 4 * cg);
    };

    auto accum = [&](const u64* buf, int off, int cnt) {
      #pragma unroll
      for (int hh = 0; hh < 4; ++hh) {
        if (hh >= cnt) break;
        const u64 x8 = buf[hh];
        uint32_t ulo = (uint32_t)x8;
        uint32_t uhi = (uint32_t)(x8 >> 32);
        const float2 f01 = __half22float2(*reinterpret_cast<__half2*>(&ulo));
        const float2 f23 = __half22float2(*reinterpret_cast<__half2*>(&uhi));
        const u64 xc[4] = {pack2(f01.x, f01.x), pack2(f01.y, f01.y),
                           pack2(f23.x, f23.x), pack2(f23.y, f23.y)};
        const int h = off + hh;
        const uint4 wa = *reinterpret_cast<const uint4*>(wvp + h * 12);
        const uint4 wb = *reinterpret_cast<const uint4*>(wvp + h * 12 + 4);
        const u64 w2[5] = {cat2(wa.x, wa.y), cat2(wa.z, wa.w),
                           cat2(wb.x, wb.y), cat2(wb.z, wb.w),
                           *reinterpret_cast<const u64*>(wvp + h * 12 + 8)};
        #pragma unroll
        for (int kk = 0; kk < 5; ++kk)
          #pragma unroll
          for (int c = 0; c < 4; ++c)
            acc[kk][c] = ffma2(w2[kk], xc[c], acc[kk][c]);
      }
    };

    // 4-wide double-buffered micro-batches: 4/4/4/4/4/3/3.
    u64 xb[4], xq[4];
    gather(xb, 0, 4);
    gather(xq, 4, 4);   accum(xb, 0, 4);
    gather(xb, 8, 4);   accum(xq, 4, 4);
    gather(xq, 12, 4);  accum(xb, 8, 4);
    gather(xb, 16, 4);  accum(xq, 12, 4);
    gather(xq, 20, 3);  accum(xb, 16, 4);
    gather(xb, 23, 3);  accum(xq, 20, 3);
    accum(xb, 23, 3);

    // Store: per k, 4 fp16 cols per lane -> one 8-B store.
    if (n < N) {
      __half* base = g_A + (size_t)n * KDIM;
      #pragma unroll
      for (int kk = 0; kk < 5; ++kk) {
        const float2 v0 = unpack2(acc[kk][0]);
        const float2 v1 = unpack2(acc[kk][1]);
        const float2 v2 = unpack2(acc[kk][2]);
        const float2 v3 = unpack2(acc[kk][3]);
        const __half2 e01 = __floats2half2_rn(v0.x, v1.x);
        const __half2 e23 = __floats2half2_rn(v2.x, v3.x);
        const __half2 o01 = __floats2half2_rn(v0.y, v1.y);
        const __half2 o23 = __floats2half2_rn(v2.y, v3.y);
        u64 we = cat2(*reinterpret_cast<const uint32_t*>(&e01),
                      *reinterpret_cast<const uint32_t*>(&e23));
        u64 wo = cat2(*reinterpret_cast<const uint32_t*>(&o01),
                      *reinterpret_cast<const uint32_t*>(&o23));
        *reinterpret_cast<u64*>(base + (2 * kk) * CIN + 4 * cg) = we;
        *reinterpret_cast<u64*>(base + (2 * kk + 1) * CIN + 4 * cg) = wo;
      }
    }
  }
}

// ───────────────────── Kernel 2: fp16 mma.sync GEMM (round-12, verbatim) ────────

constexpr int KT      = 64;
constexpr int PITCH   = 144;
constexpr int TSZ     = 128 * PITCH;       // 18432 B
constexpr int STAGE   = 2 * TSZ;           // 36864 B
constexpr int NSTAGES = 3;
constexpr int GSMEM   = NSTAGES * STAGE;   // 110592 B
constexpr int NKT     = KDIM / KT;         // 10
constexpr int GNT     = 128;

__global__ void __launch_bounds__(GNT, 2)
gemm_kernel(float* __restrict__ out, int N)
{
  extern __shared__ char sm[];
  const uint32_t sb = smem_u32(sm);
  const int tid  = threadIdx.x;
  const int lane = tid & 31;
  const int wid  = tid >> 5;
  const int wr   = wid >> 1;
  const int wc   = wid & 1;
  const size_t n0 = (size_t)blockIdx.x * 128;

  auto load_stage = [&](int st, int kc) {
    const uint32_t base = sb + st * STAGE;
    #pragma unroll
    for (int i = 0; i < 8; ++i) {
      const int id = tid + i * GNT;
      const int r  = id >> 3;
      const int c  = id & 7;
      const uint32_t d = r * PITCH + c * 16;
      cp16(base + d,       g_A + (n0 + r) * KDIM + kc * KT + c * 8);
      cp16(base + TSZ + d, g_B + (size_t)r * KDIM + kc * KT + c * 8);
    }
  };

  load_stage(0, 0); cp_commit();
  load_stage(1, 1); cp_commit();

  const int arow  = lane & 15;
  const int acolB = (lane >> 4) * 16;
  const int brow  = (lane & 7) + ((lane >> 4) << 3);
  const int bcolB = ((lane >> 3) & 1) * 16;

  float acc[4][8][4];
  #pragma unroll
  for (int mi = 0; mi < 4; ++mi)
    #pragma unroll
    for (int ni = 0; ni < 8; ++ni)
      #pragma unroll
      for (int j = 0; j < 4; ++j) acc[mi][ni][j] = 0.f;

  for (int kc = 0; kc < NKT; ++kc) {
    const int st = kc % NSTAGES;
    cp_wait1();
    __syncthreads();

    if (kc + 2 < NKT) load_stage((kc + 2) % NSTAGES, kc + 2);
    cp_commit();

    const uint32_t tA = sb + st * STAGE;
    const uint32_t tB = sb + st * STAGE + TSZ;

    #pragma unroll
    for (int ks = 0; ks < 4; ++ks) {
      uint32_t ah[4][4], bh[8][2];
      #pragma unroll
      for (int mi = 0; mi < 4; ++mi) {
        const uint32_t ao =
            (wr * 64 + mi * 16 + arow) * PITCH + ks * 32 + acolB;
        ldm4(ah[mi], tA + ao);
      }
      #pragma unroll
      for (int bi = 0; bi < 4; ++bi) {
        const uint32_t bo =
            (wc * 64 + bi * 16 + brow) * PITCH + ks * 32 + bcolB;
        uint32_t t4[4];
        ldm4(t4, tB + bo);
        bh[2 * bi][0] = t4[0]; bh[2 * bi][1] = t4[1];
        bh[2 * bi + 1][0] = t4[2]; bh[2 * bi + 1][1] = t4[3];
      }
      #pragma unroll
      for (int mi = 0; mi < 4; ++mi)
        #pragma unroll
        for (int ni = 0; ni < 8; ++ni)
          mma16816(acc[mi][ni], ah[mi], bh[ni]);
    }
  }

  const int trow = lane >> 2;
  const int tcol = (lane & 3) * 2;
  #pragma unroll
  for (int mi = 0; mi < 4; ++mi) {
    const size_t row = n0 + wr * 64 + mi * 16 + trow;
    #pragma unroll
    for (int ni = 0; ni < 8; ++ni) {
      const int col = wc * 64 + ni * 8 + tcol;
      if (row < (size_t)N) {
        *reinterpret_cast<float2*>(out + row * COUT + col) =
            make_float2(acc[mi][ni][0], acc[mi][ni][1]);
        *reinterpret_cast<float2*>(out + (row + 8) * COUT + col) =
            make_float2(acc[mi][ni][2], acc[mi][ni][3]);
      }
    }
  }
}

}  // namespace

// ───────────────────────────── launch ─────────────────────────────

extern "C" void kernel_launch(void* const* d_in, const int* in_sizes, int n_in,
                              void* d_out, int out_size) {
  const float* q_pts = (const float*)d_in[0];
  const float* s_pts = (const float*)d_in[1];
  const float* x     = (const float*)d_in[2];
  const float* genW  = (const float*)d_in[3];
  const float* genB  = (const float*)d_in[4];
  const float* wts   = (const float*)d_in[5];
  const int*   inds  = (const int*)d_in[6];
  float* out = (float*)d_out;

  int N  = in_sizes[0] / 3;
  const int Ns = in_sizes[1] / 3;
  if (N > MAXN) N = MAXN;

  cudaFuncSetAttribute(gemm_kernel,
                       cudaFuncAttributeMaxDynamicSharedMemorySize, GSMEM);

  prep_kernel<<<1024, 256>>>(x, wts, N * CIN);

  const int grid1 = (N + TILE - 1) / TILE;
  producer_kernel<<<grid1, NT>>>(q_pts, s_pts, genW, genB, inds, N, Ns);

  const int grid3 = (N + 127) / 128;
  gemm_kernel<<<grid3, GNT, GSMEM>>>(out, N);
}